// round 8
// baseline (speedup 1.0000x reference)
#include <cuda_runtime.h>

#define KNN      11
#define NPTS     50000
#define NSP      4000
#define NB       2
#define G        20
#define NCELL    (G*G*G)                  // 8000
#define NBIN     32768                    // morton bins (5 bits/axis)
#define CHUNK    ((NCELL + 255) / 256)    // 32
#define CHUNKM   (NBIN / 256)             // 128
#define TMAIN    256
#define BLKS_MAIN ((NPTS + TMAIN - 1) / TMAIN)

// ---------------- device scratch (no allocations allowed) ----------------
__device__ float4 g_spk[NB][NSP];            // cell-sorted sites, w = int_as_float(sidx<<12)
__device__ unsigned short g_cst[NB][NCELL + 1];
__device__ float  g_box[NB][9];              // mn[3], h[3], inv_h[3]
__device__ int    g_pcnt[NB][NBIN];
__device__ int    g_pcur[NB][NBIN];
__device__ float4 g_pts[NB][NPTS];           // morton-sorted queries (w = orig idx)

__device__ __forceinline__ int cell_of(float x, float y, float z, const float* bx) {
    int cx = (int)((x - bx[0]) * bx[6]); cx = min(G - 1, max(0, cx));
    int cy = (int)((y - bx[1]) * bx[7]); cy = min(G - 1, max(0, cy));
    int cz = (int)((z - bx[2]) * bx[8]); cz = min(G - 1, max(0, cz));
    return (cx * G + cy) * G + cz;
}

__device__ __forceinline__ unsigned mexp(unsigned v) {
    v &= 0x3ff;
    v = (v | (v << 16)) & 0x030000FF;
    v = (v | (v << 8))  & 0x0300F00F;
    v = (v | (v << 4))  & 0x030C30C3;
    v = (v | (v << 2))  & 0x09249249;
    return v;
}
__device__ __forceinline__ unsigned morton_of(float x, float y, float z, const float* bx) {
    int cx = (int)((x - bx[0]) * bx[6]); cx = min(G - 1, max(0, cx));
    int cy = (int)((y - bx[1]) * bx[7]); cy = min(G - 1, max(0, cy));
    int cz = (int)((z - bx[2]) * bx[8]); cz = min(G - 1, max(0, cz));
    return mexp(cx) | (mexp(cy) << 1) | (mexp(cz) << 2);
}

// ---------------- kernel 1: bin sites into grid (one block per batch) ----------------
static constexpr int SM_SETUP = (NCELL + NCELL + 1 + 256) * 4 + 48 * 4;

__global__ void k_setup_sites(const float* __restrict__ spoints) {
    extern __shared__ int sm[];
    int*   cnt = sm;                  // NCELL
    int*   st  = cnt + NCELL;         // NCELL+1
    int*   tot = st + NCELL + 1;      // 256
    float* red = (float*)(tot + 256); // 48
    __shared__ float sbox[9];

    const int b = blockIdx.x, tid = threadIdx.x;
    const float* sp = spoints + (size_t)b * NSP * 3;

    for (int c = tid; c < NBIN; c += blockDim.x) g_pcnt[b][c] = 0;

    float mnx = 3e38f, mny = 3e38f, mnz = 3e38f;
    float mxx = -3e38f, mxy = -3e38f, mxz = -3e38f;
    for (int i = tid; i < NSP; i += blockDim.x) {
        float x = sp[3*i], y = sp[3*i+1], z = sp[3*i+2];
        mnx = fminf(mnx, x); mxx = fmaxf(mxx, x);
        mny = fminf(mny, y); mxy = fmaxf(mxy, y);
        mnz = fminf(mnz, z); mxz = fmaxf(mxz, z);
    }
#pragma unroll
    for (int o = 16; o; o >>= 1) {
        mnx = fminf(mnx, __shfl_xor_sync(0xffffffffu, mnx, o));
        mny = fminf(mny, __shfl_xor_sync(0xffffffffu, mny, o));
        mnz = fminf(mnz, __shfl_xor_sync(0xffffffffu, mnz, o));
        mxx = fmaxf(mxx, __shfl_xor_sync(0xffffffffu, mxx, o));
        mxy = fmaxf(mxy, __shfl_xor_sync(0xffffffffu, mxy, o));
        mxz = fmaxf(mxz, __shfl_xor_sync(0xffffffffu, mxz, o));
    }
    int w = tid >> 5;
    if ((tid & 31) == 0) {
        red[w] = mnx; red[8 + w] = mny; red[16 + w] = mnz;
        red[24 + w] = mxx; red[32 + w] = mxy; red[40 + w] = mxz;
    }
    __syncthreads();
    if (tid == 0) {
        float a0 = red[0], a1 = red[8], a2 = red[16], a3 = red[24], a4 = red[32], a5 = red[40];
        for (int i = 1; i < 8; i++) {
            a0 = fminf(a0, red[i]);      a1 = fminf(a1, red[8 + i]);  a2 = fminf(a2, red[16 + i]);
            a3 = fmaxf(a3, red[24 + i]); a4 = fmaxf(a4, red[32 + i]); a5 = fmaxf(a5, red[40 + i]);
        }
        float hx = (a3 - a0) * (1.0f / G) * 1.000001f + 1e-30f;
        float hy = (a4 - a1) * (1.0f / G) * 1.000001f + 1e-30f;
        float hz = (a5 - a2) * (1.0f / G) * 1.000001f + 1e-30f;
        sbox[0] = a0; sbox[1] = a1; sbox[2] = a2;
        sbox[3] = hx; sbox[4] = hy; sbox[5] = hz;
        sbox[6] = 1.0f / hx; sbox[7] = 1.0f / hy; sbox[8] = 1.0f / hz;
        for (int i = 0; i < 9; i++) g_box[b][i] = sbox[i];
    }
    __syncthreads();

    for (int c = tid; c < NCELL; c += blockDim.x) cnt[c] = 0;
    __syncthreads();
    for (int i = tid; i < NSP; i += blockDim.x) {
        int c = cell_of(sp[3*i], sp[3*i+1], sp[3*i+2], sbox);
        atomicAdd(&cnt[c], 1);
    }
    __syncthreads();

    int c0 = tid * CHUNK, s = 0;
    for (int j = 0; j < CHUNK; j++) { int c = c0 + j; if (c < NCELL) s += cnt[c]; }
    tot[tid] = s;
    __syncthreads();
    if (tid == 0) { int run = 0; for (int i = 0; i < 256; i++) { int v = tot[i]; tot[i] = run; run += v; } }
    __syncthreads();
    int run = tot[tid];
    for (int j = 0; j < CHUNK; j++) { int c = c0 + j; if (c < NCELL) { st[c] = run; run += cnt[c]; } }
    __syncthreads();
    if (tid == 0) st[NCELL] = NSP;
    __syncthreads();

    for (int c = tid; c <= NCELL; c += blockDim.x) g_cst[b][c] = (unsigned short)st[c];
    for (int c = tid; c < NCELL; c += blockDim.x) cnt[c] = st[c];   // cnt becomes cursor
    __syncthreads();

    for (int i = tid; i < NSP; i += blockDim.x) {
        float x = sp[3*i], y = sp[3*i+1], z = sp[3*i+2];
        int c = cell_of(x, y, z, sbox);
        int pos = atomicAdd(&cnt[c], 1);
        g_spk[b][pos] = make_float4(x, y, z, __int_as_float(i << 12));
    }
}

// ---------------- kernel 2: count queries per MORTON bin ----------------
__global__ void k_count_pts(const float* __restrict__ points) {
    const int b = blockIdx.y;
    const int p = blockIdx.x * blockDim.x + threadIdx.x;
    if (p >= NPTS) return;
    const float* pp = points + ((size_t)b * NPTS + p) * 3;
    float bx[9];
#pragma unroll
    for (int i = 0; i < 9; i++) bx[i] = g_box[b][i];
    atomicAdd(&g_pcnt[b][morton_of(pp[0], pp[1], pp[2], bx)], 1);
}

// ---------------- kernel 3: exclusive scan over morton bins -> cursors ----------------
__global__ void k_init_cursors() {
    const int b = blockIdx.x, tid = threadIdx.x;
    __shared__ int tot[256];
    int c0 = tid * CHUNKM, s = 0;
    for (int j = 0; j < CHUNKM; j++) s += g_pcnt[b][c0 + j];
    tot[tid] = s;
    __syncthreads();
    if (tid == 0) { int run = 0; for (int i = 0; i < 256; i++) { int v = tot[i]; tot[i] = run; run += v; } }
    __syncthreads();
    int run = tot[tid];
    for (int j = 0; j < CHUNKM; j++) { int c = c0 + j; g_pcur[b][c] = run; run += g_pcnt[b][c]; }
}

// ---------------- kernel 4: scatter queries into morton-sorted order ----------------
__global__ void k_scatter_pts(const float* __restrict__ points) {
    const int b = blockIdx.y;
    const int p = blockIdx.x * blockDim.x + threadIdx.x;
    if (p >= NPTS) return;
    const float* pp = points + ((size_t)b * NPTS + p) * 3;
    float x = pp[0], y = pp[1], z = pp[2];
    float bx[9];
#pragma unroll
    for (int i = 0; i < 9; i++) bx[i] = g_box[b][i];
    int pos = atomicAdd(&g_pcur[b][morton_of(x, y, z, bx)], 1);
    g_pts[b][pos] = make_float4(x, y, z, __int_as_float(p));
}

// ---------------- kernel 5: main — warp-uniform union-box traversal (morton-tight) ----------------
static constexpr int SM_MAIN = NSP * 16 + 16 * 4 + (NCELL + 1) * 2;  // 80066

__global__ __launch_bounds__(TMAIN, 2) void k_main(float* __restrict__ out) {
    extern __shared__ float smf[];
    float4* spk = (float4*)smf;                        // NSP float4
    float*  sbb = (float*)(spk + NSP);                 // 9 floats (+pad)
    unsigned short* cst = (unsigned short*)(sbb + 16); // NCELL+1

    const int b = blockIdx.y, tid = threadIdx.x;
    for (int i = tid; i < NSP; i += TMAIN) spk[i] = g_spk[b][i];
    for (int i = tid; i <= NCELL; i += TMAIN) cst[i] = g_cst[b][i];
    if (tid < 9) sbb[tid] = g_box[b][tid];
    __syncthreads();

    int t = blockIdx.x * TMAIN + tid;
    const bool valid = (t < NPTS);
    if (!valid) t = NPTS - 1;

    const float4 P = g_pts[b][t];
    const float px = P.x, py = P.y, pz = P.z;
    const int orig = __float_as_int(P.w);

    const float mnx = sbb[0], mny = sbb[1], mnz = sbb[2];
    const float hx = sbb[3], hy = sbb[4], hz = sbb[5];
    const int cx = min(G - 1, max(0, (int)((px - mnx) * sbb[6])));
    const int cy = min(G - 1, max(0, (int)((py - mny) * sbb[7])));
    const int cz = min(G - 1, max(0, (int)((pz - mnz) * sbb[8])));

    float bd[KNN];
    int   bo[KNN];   // key = (orig_site_idx << 12) | sorted_pos — lex order == jax tie-break
#pragma unroll
    for (int k = 0; k < KNN; k++) { bd[k] = 3.4e38f; bo[k] = 0x7FFFFFFF; }

    // Warp union of home cells — tight because queries are MORTON-sorted.
    const unsigned FULL = 0xffffffffu;
    const int cxm = __reduce_min_sync(FULL, cx), cxM = __reduce_max_sync(FULL, cx);
    const int cym = __reduce_min_sync(FULL, cy), cyM = __reduce_max_sync(FULL, cy);
    const int czm = __reduce_min_sync(FULL, cz), czM = __reduce_max_sync(FULL, cz);

    int pxl = 1, pxh = 0, pyl = 1, pyh = 0, pzl = 1, pzh = 0;  // empty prev box
    bool ldone = false;

    for (int r = 0; ; r++) {
        const int xlo = max(cxm - r, 0), xhi = min(cxM + r, G - 1);
        const int ylo = max(cym - r, 0), yhi = min(cyM + r, G - 1);
        const int zlo = max(czm - r, 0), zhi = min(czM + r, G - 1);

        for (int X = xlo; X <= xhi; X++) {
            const bool xin = (X >= pxl) && (X <= pxh);
            for (int Y = ylo; Y <= yhi; Y++) {
                const bool yin = xin && (Y >= pyl) && (Y <= pyh);
                const int cbase = (X * G + Y) * G;
                for (int Z = zlo; Z <= zhi; Z++) {
                    if (yin && Z >= pzl && Z <= pzh) continue;   // visited (uniform)
                    const int c = cbase + Z;
                    const int m0 = cst[c], m1 = cst[c + 1];      // uniform -> broadcast
                    if (!ldone) {
                        for (int m = m0; m < m1; m++) {
                            const float4 S = spk[m];             // LDS.128 broadcast
                            const float dx = px - S.x;
                            const float dy = py - S.y;
                            const float dz = pz - S.z;
                            const float d2 = fmaf(dz, dz, fmaf(dy, dy, dx * dx));
                            if (d2 <= bd[KNN - 1]) {
                                float d = d2;
                                int kk = __float_as_int(S.w) | m;
#pragma unroll
                                for (int k = 0; k < KNN; k++) {
                                    const bool sw = (d < bd[k]) || ((d == bd[k]) && (kk < bo[k]));
                                    if (sw) {
                                        const float td = bd[k]; bd[k] = d;  d = td;
                                        const int   ti = bo[k]; bo[k] = kk; kk = ti;
                                    }
                                }
                            }
                        }
                    }
                }
            }
        }

        const bool full = (xlo == 0 && xhi == G - 1 && ylo == 0 && yhi == G - 1 &&
                           zlo == 0 && zhi == G - 1);
        if (!ldone) {
            // Per-lane ring bound vs the warp's visited box; clamped faces need no bound.
            float bnd = 3.0e38f;
            if (xlo > 0)     bnd = fminf(bnd, px - (mnx + (float)xlo * hx));
            if (xhi < G - 1) bnd = fminf(bnd, (mnx + (float)(xhi + 1) * hx) - px);
            if (ylo > 0)     bnd = fminf(bnd, py - (mny + (float)ylo * hy));
            if (yhi < G - 1) bnd = fminf(bnd, (mny + (float)(yhi + 1) * hy) - py);
            if (zlo > 0)     bnd = fminf(bnd, pz - (mnz + (float)zlo * hz));
            if (zhi < G - 1) bnd = fminf(bnd, (mnz + (float)(zhi + 1) * hz) - pz);
            ldone = full || (bd[KNN - 1] < 3.0e38f && bnd > 0.0f &&
                             bnd * bnd >= bd[KNN - 1] * 1.0002f);
        }
        if (__all_sync(FULL, ldone) || full) break;
        pxl = xlo; pxh = xhi; pyl = ylo; pyh = yhi; pzl = zlo; pzh = zhi;
    }

    // Voronoi-edge epilogue on the 11 selected sites (slots 1..10 order irrelevant: min)
    const int p0 = bo[0] & 4095;
    const float4 C = spk[p0];
    const float tx = px - C.x, ty = py - C.y, tz = pz - C.z;
    float best = 3.4e38f;
#pragma unroll
    for (int j = 1; j < KNN; j++) {
        const int pj = bo[j] & 4095;
        const float4 E = spk[pj];
        const float ex = E.x - C.x, ey = E.y - C.y, ez = E.z - C.z;
        const float el2 = fmaf(ez, ez, fmaf(ey, ey, ex * ex));
        const float dp  = fmaf(tz, ez, fmaf(ty, ey, tx * ex));
        const float tt  = fmaf(-0.5f, el2, dp) * rsqrtf(el2);  // (dp - el2/2)/sqrt(el2)
        best = fminf(best, tt * tt);
    }
    if (valid) out[(size_t)b * NPTS + orig] = best;
}

// ---------------- launch ----------------
extern "C" void kernel_launch(void* const* d_in, const int* in_sizes, int n_in,
                              void* d_out, int out_size)
{
    const float* points  = (const float*)d_in[0];
    const float* spoints = (const float*)d_in[1];
    float* out = (float*)d_out;

    cudaFuncSetAttribute(k_setup_sites, cudaFuncAttributeMaxDynamicSharedMemorySize, SM_SETUP);
    cudaFuncSetAttribute(k_main,        cudaFuncAttributeMaxDynamicSharedMemorySize, SM_MAIN);

    k_setup_sites<<<NB, 256, SM_SETUP>>>(spoints);
    dim3 gp((NPTS + 255) / 256, NB);
    k_count_pts<<<gp, 256>>>(points);
    k_init_cursors<<<NB, 256>>>();
    k_scatter_pts<<<gp, 256>>>(points);
    k_main<<<dim3(BLKS_MAIN, NB), TMAIN, SM_MAIN>>>(out);
}

// round 9
// speedup vs baseline: 2.7962x; 2.7962x over previous
#include <cuda_runtime.h>

#define KNN      11
#define NPTS     50000
#define NSP      4000
#define NB       2
#define G        20
#define NCELL    (G*G*G)                  // 8000
#define CHUNK    ((NCELL + 255) / 256)    // 32
#define TMAIN    256
#define BLKS_MAIN ((NPTS + TMAIN - 1) / TMAIN)

// ---------------- device scratch (no allocations allowed) ----------------
__device__ float4         g_spk[NB][NSP];       // cell-sorted sites, w = int_as_float(sidx<<12)
__device__ unsigned short g_cst[NB][NCELL + 1]; // site cell start offsets
__device__ float          g_box[NB][9];         // mn[3], h[3], inv_h[3]
__device__ int            g_pcnt[NB][NCELL];
__device__ int            g_pcur[NB][NCELL];
__device__ float4         g_pts[NB][NPTS];      // cell-sorted queries (w = orig idx)

__device__ __forceinline__ int cell_of(float x, float y, float z, const float* bx) {
    int cx = (int)((x - bx[0]) * bx[6]); cx = min(G - 1, max(0, cx));
    int cy = (int)((y - bx[1]) * bx[7]); cy = min(G - 1, max(0, cy));
    int cz = (int)((z - bx[2]) * bx[8]); cz = min(G - 1, max(0, cz));
    return (cx * G + cy) * G + cz;
}

// ---------------- kernel 1: bin sites into grid (one block per batch) ----------------
static constexpr int SM_SETUP = (NCELL + NCELL + 1 + 256) * 4 + 48 * 4;

__global__ void k_setup_sites(const float* __restrict__ spoints) {
    extern __shared__ int sm[];
    int*   cnt = sm;                  // NCELL
    int*   st  = cnt + NCELL;         // NCELL+1
    int*   tot = st + NCELL + 1;      // 256
    float* red = (float*)(tot + 256); // 48
    __shared__ float sbox[9];

    const int b = blockIdx.x, tid = threadIdx.x;
    const float* sp = spoints + (size_t)b * NSP * 3;

    for (int c = tid; c < NCELL; c += blockDim.x) g_pcnt[b][c] = 0;

    float mnx = 3e38f, mny = 3e38f, mnz = 3e38f;
    float mxx = -3e38f, mxy = -3e38f, mxz = -3e38f;
    for (int i = tid; i < NSP; i += blockDim.x) {
        float x = sp[3*i], y = sp[3*i+1], z = sp[3*i+2];
        mnx = fminf(mnx, x); mxx = fmaxf(mxx, x);
        mny = fminf(mny, y); mxy = fmaxf(mxy, y);
        mnz = fminf(mnz, z); mxz = fmaxf(mxz, z);
    }
#pragma unroll
    for (int o = 16; o; o >>= 1) {
        mnx = fminf(mnx, __shfl_xor_sync(0xffffffffu, mnx, o));
        mny = fminf(mny, __shfl_xor_sync(0xffffffffu, mny, o));
        mnz = fminf(mnz, __shfl_xor_sync(0xffffffffu, mnz, o));
        mxx = fmaxf(mxx, __shfl_xor_sync(0xffffffffu, mxx, o));
        mxy = fmaxf(mxy, __shfl_xor_sync(0xffffffffu, mxy, o));
        mxz = fmaxf(mxz, __shfl_xor_sync(0xffffffffu, mxz, o));
    }
    int w = tid >> 5;
    if ((tid & 31) == 0) {
        red[w] = mnx; red[8 + w] = mny; red[16 + w] = mnz;
        red[24 + w] = mxx; red[32 + w] = mxy; red[40 + w] = mxz;
    }
    __syncthreads();
    if (tid == 0) {
        float a0 = red[0], a1 = red[8], a2 = red[16], a3 = red[24], a4 = red[32], a5 = red[40];
        for (int i = 1; i < 8; i++) {
            a0 = fminf(a0, red[i]);      a1 = fminf(a1, red[8 + i]);  a2 = fminf(a2, red[16 + i]);
            a3 = fmaxf(a3, red[24 + i]); a4 = fmaxf(a4, red[32 + i]); a5 = fmaxf(a5, red[40 + i]);
        }
        float hx = (a3 - a0) * (1.0f / G) * 1.000001f + 1e-30f;
        float hy = (a4 - a1) * (1.0f / G) * 1.000001f + 1e-30f;
        float hz = (a5 - a2) * (1.0f / G) * 1.000001f + 1e-30f;
        sbox[0] = a0; sbox[1] = a1; sbox[2] = a2;
        sbox[3] = hx; sbox[4] = hy; sbox[5] = hz;
        sbox[6] = 1.0f / hx; sbox[7] = 1.0f / hy; sbox[8] = 1.0f / hz;
        for (int i = 0; i < 9; i++) g_box[b][i] = sbox[i];
    }
    __syncthreads();

    for (int c = tid; c < NCELL; c += blockDim.x) cnt[c] = 0;
    __syncthreads();
    for (int i = tid; i < NSP; i += blockDim.x) {
        int c = cell_of(sp[3*i], sp[3*i+1], sp[3*i+2], sbox);
        atomicAdd(&cnt[c], 1);
    }
    __syncthreads();

    int c0 = tid * CHUNK, s = 0;
    for (int j = 0; j < CHUNK; j++) { int c = c0 + j; if (c < NCELL) s += cnt[c]; }
    tot[tid] = s;
    __syncthreads();
    if (tid == 0) { int run = 0; for (int i = 0; i < 256; i++) { int v = tot[i]; tot[i] = run; run += v; } }
    __syncthreads();
    int run = tot[tid];
    for (int j = 0; j < CHUNK; j++) { int c = c0 + j; if (c < NCELL) { st[c] = run; run += cnt[c]; } }
    __syncthreads();
    if (tid == 0) st[NCELL] = NSP;
    __syncthreads();

    for (int c = tid; c <= NCELL; c += blockDim.x) g_cst[b][c] = (unsigned short)st[c];
    for (int c = tid; c < NCELL; c += blockDim.x) cnt[c] = st[c];   // cnt becomes cursor
    __syncthreads();

    for (int i = tid; i < NSP; i += blockDim.x) {
        float x = sp[3*i], y = sp[3*i+1], z = sp[3*i+2];
        int c = cell_of(x, y, z, sbox);
        int pos = atomicAdd(&cnt[c], 1);
        g_spk[b][pos] = make_float4(x, y, z, __int_as_float(i << 12));
    }
}

// ---------------- kernel 2: count queries per cell ----------------
__global__ void k_count_pts(const float* __restrict__ points) {
    const int b = blockIdx.y;
    const int p = blockIdx.x * blockDim.x + threadIdx.x;
    if (p >= NPTS) return;
    const float* pp = points + ((size_t)b * NPTS + p) * 3;
    float bx[9];
#pragma unroll
    for (int i = 0; i < 9; i++) bx[i] = g_box[b][i];
    atomicAdd(&g_pcnt[b][cell_of(pp[0], pp[1], pp[2], bx)], 1);
}

// ---------------- kernel 3: scan query counts -> cursors ----------------
__global__ void k_init_cursors() {
    const int b = blockIdx.x, tid = threadIdx.x;
    __shared__ int tot[256];
    int c0 = tid * CHUNK, s = 0;
    for (int j = 0; j < CHUNK; j++) { int c = c0 + j; if (c < NCELL) s += g_pcnt[b][c]; }
    tot[tid] = s;
    __syncthreads();
    if (tid == 0) { int run = 0; for (int i = 0; i < 256; i++) { int v = tot[i]; tot[i] = run; run += v; } }
    __syncthreads();
    int run = tot[tid];
    for (int j = 0; j < CHUNK; j++) { int c = c0 + j; if (c < NCELL) { g_pcur[b][c] = run; run += g_pcnt[b][c]; } }
}

// ---------------- kernel 4: scatter queries into cell-sorted order ----------------
__global__ void k_scatter_pts(const float* __restrict__ points) {
    const int b = blockIdx.y;
    const int p = blockIdx.x * blockDim.x + threadIdx.x;
    if (p >= NPTS) return;
    const float* pp = points + ((size_t)b * NPTS + p) * 3;
    float x = pp[0], y = pp[1], z = pp[2];
    float bx[9];
#pragma unroll
    for (int i = 0; i < 9; i++) bx[i] = g_box[b][i];
    int pos = atomicAdd(&g_pcur[b][cell_of(x, y, z, bx)], 1);
    g_pts[b][pos] = make_float4(x, y, z, __int_as_float(p));
}

// ---------------- kernel 5: main — count-threshold + warp-voted column sweep ----------------
static constexpr int SM_MAIN = NSP * 16 + 16 * 4 + (NCELL + 1) * 2;  // 80066

__global__ __launch_bounds__(TMAIN, 2) void k_main(float* __restrict__ out) {
    extern __shared__ float smf[];
    float4* spk = (float4*)smf;                        // NSP float4
    float*  sbb = (float*)(spk + NSP);                 // 9 floats (+pad)
    unsigned short* cst = (unsigned short*)(sbb + 16); // NCELL+1

    const int b = blockIdx.y, tid = threadIdx.x;
    for (int i = tid; i < NSP; i += TMAIN) spk[i] = g_spk[b][i];
    for (int i = tid; i <= NCELL; i += TMAIN) cst[i] = g_cst[b][i];
    if (tid < 9) sbb[tid] = g_box[b][tid];
    __syncthreads();

    int t = blockIdx.x * TMAIN + tid;
    const bool valid = (t < NPTS);
    if (!valid) t = NPTS - 1;            // duplicate last point; keeps warp full

    const float4 P = g_pts[b][t];
    const float px = P.x, py = P.y, pz = P.z;
    const int orig = __float_as_int(P.w);

    const float mnx = sbb[0], mny = sbb[1], mnz = sbb[2];
    const float hx = sbb[3], hy = sbb[4], hz = sbb[5];
    const float ihx = sbb[6], ihy = sbb[7], ihz = sbb[8];
    const int cx = min(G - 1, max(0, (int)((px - mnx) * ihx)));
    const int cy = min(G - 1, max(0, (int)((py - mny) * ihy)));
    const int cz = min(G - 1, max(0, (int)((pz - mnz) * ihz)));

    // ---- Phase A: count-only expanding box -> upper bound T on 11th-NN d2 ----
    int xlo, xhi, ylo, yhi, zlo, zhi;
    for (int r = 0; ; r++) {
        xlo = max(cx - r, 0); xhi = min(cx + r, G - 1);
        ylo = max(cy - r, 0); yhi = min(cy + r, G - 1);
        zlo = max(cz - r, 0); zhi = min(cz + r, G - 1);
        int count = 0;
        for (int X = xlo; X <= xhi; X++) {
            const int rb = X * G;
            for (int Y = ylo; Y <= yhi; Y++) {
                const int cb = (rb + Y) * G;
                count += (int)cst[cb + zhi + 1] - (int)cst[cb + zlo];
            }
        }
        if (count >= KNN) break;
        if (xlo == 0 && xhi == G - 1 && ylo == 0 && yhi == G - 1 &&
            zlo == 0 && zhi == G - 1) break;   // whole grid (count = NSP >= 11)
    }
    const float fx = fmaxf(px - (mnx + (float)xlo * hx), (mnx + (float)(xhi + 1) * hx) - px);
    const float fy = fmaxf(py - (mny + (float)ylo * hy), (mny + (float)(yhi + 1) * hy) - py);
    const float fz = fmaxf(pz - (mnz + (float)zlo * hz), (mnz + (float)(zhi + 1) * hz) - pz);
    const float T  = (fmaf(fx, fx, fmaf(fy, fy, fz * fz))) * 1.0005f;  // fp-safe upper bound
    const float sT = sqrtf(T);

    // per-lane candidate cell windows (conservative truncation + clamps)
    const int qxl = min(G - 1, max(0, (int)((px - sT - mnx) * ihx)));
    const int qxh = min(G - 1, max(0, (int)((px + sT - mnx) * ihx)));
    const int qyl = min(G - 1, max(0, (int)((py - sT - mny) * ihy)));
    const int qyh = min(G - 1, max(0, (int)((py + sT - mny) * ihy)));
    const int qzl = min(G - 1, max(0, (int)((pz - sT - mnz) * ihz)));
    const int qzh = min(G - 1, max(0, (int)((pz + sT - mnz) * ihz)));

    const unsigned FULL = 0xffffffffu;
    const int WXl = __reduce_min_sync(FULL, qxl), WXh = __reduce_max_sync(FULL, qxh);
    const int WYl = __reduce_min_sync(FULL, qyl), WYh = __reduce_max_sync(FULL, qyh);

    float bd[KNN];
    int   bo[KNN];   // key = (orig_site_idx << 12) | sorted_pos — lex order == jax tie-break
#pragma unroll
    for (int k = 0; k < KNN; k++) { bd[k] = 3.4e38f; bo[k] = 0x7FFFFFFF; }

    // ---- Phase B: warp-uniform column sweep with per-lane rectangle pruning ----
    for (int X = WXl; X <= WXh; X++) {
        const float clx = mnx + (float)X * hx;
        const float dxx = fmaxf(0.0f, fmaxf(clx - px, px - (clx + hx)));
        const float dxx2 = dxx * dxx;
        if (__all_sync(FULL, dxx2 > T)) continue;        // whole X-slab too far for every lane
        for (int Y = WYl; Y <= WYh; Y++) {
            const float cly = mny + (float)Y * hy;
            const float dyy = fmaxf(0.0f, fmaxf(cly - py, py - (cly + hy)));
            const float dxy2 = fmaf(dyy, dyy, dxx2);
            const bool inter = (dxy2 <= T);
            if (__any_sync(FULL, inter)) {
                const int zl = inter ? qzl : 1000;
                const int zh = inter ? qzh : -1000;
                const int Zl = max(0, __reduce_min_sync(FULL, zl));
                const int Zh = min(G - 1, __reduce_max_sync(FULL, zh));
                const int cb = (X * G + Y) * G;
                const int m0 = cst[cb + Zl], m1 = cst[cb + Zh + 1];  // uniform -> broadcast
                for (int m = m0; m < m1; m++) {
                    const float4 S = spk[m];                         // LDS.128 broadcast
                    const float dx = px - S.x;
                    const float dy = py - S.y;
                    const float dz = pz - S.z;
                    const float d2 = fmaf(dz, dz, fmaf(dy, dy, dx * dx));
                    if (d2 <= bd[KNN - 1]) {
                        float d = d2;
                        int kk = __float_as_int(S.w) | m;
#pragma unroll
                        for (int k = 0; k < KNN; k++) {
                            const bool sw = (d < bd[k]) || ((d == bd[k]) && (kk < bo[k]));
                            if (sw) {
                                const float td = bd[k]; bd[k] = d;  d = td;
                                const int   ti = bo[k]; bo[k] = kk; kk = ti;
                            }
                        }
                    }
                }
            }
        }
    }

    // ---- Voronoi-edge epilogue on the 11 selected sites ----
    const int p0 = bo[0] & 4095;
    const float4 C = spk[p0];
    const float tx = px - C.x, ty = py - C.y, tz = pz - C.z;
    float best = 3.4e38f;
#pragma unroll
    for (int j = 1; j < KNN; j++) {
        const int pj = bo[j] & 4095;
        const float4 E = spk[pj];
        const float ex = E.x - C.x, ey = E.y - C.y, ez = E.z - C.z;
        const float el2 = fmaf(ez, ez, fmaf(ey, ey, ex * ex));
        const float dp  = fmaf(tz, ez, fmaf(ty, ey, tx * ex));
        const float tt  = fmaf(-0.5f, el2, dp) * rsqrtf(el2);  // (dp - el2/2)/sqrt(el2)
        best = fminf(best, tt * tt);
    }
    if (valid) out[(size_t)b * NPTS + orig] = best;
}

// ---------------- launch ----------------
extern "C" void kernel_launch(void* const* d_in, const int* in_sizes, int n_in,
                              void* d_out, int out_size)
{
    const float* points  = (const float*)d_in[0];
    const float* spoints = (const float*)d_in[1];
    float* out = (float*)d_out;

    cudaFuncSetAttribute(k_setup_sites, cudaFuncAttributeMaxDynamicSharedMemorySize, SM_SETUP);
    cudaFuncSetAttribute(k_main,        cudaFuncAttributeMaxDynamicSharedMemorySize, SM_MAIN);

    k_setup_sites<<<NB, 256, SM_SETUP>>>(spoints);
    dim3 gp((NPTS + 255) / 256, NB);
    k_count_pts<<<gp, 256>>>(points);
    k_init_cursors<<<NB, 256>>>();
    k_scatter_pts<<<gp, 256>>>(points);
    k_main<<<dim3(BLKS_MAIN, NB), TMAIN, SM_MAIN>>>(out);
}